// round 7
// baseline (speedup 1.0000x reference)
#include <cuda_runtime.h>
#include <cuda_fp16.h>

#define NN 100000
#define NE 1000000
#define NTHR 256

// Scratch.
// P1h: fp16 table, one 128B row per node: halfs[0..39]=P1[o*4+k], halfs[40..49]=Q1[o]
// g_h1: root1 term per node, 16-float rows (cols 0..9 used)
// g_S : per node: attr-sum[0..3], out-degree at [4] (8-float rows)
__device__ float4 g_P1h[(size_t)NN * 8];
__device__ float4 g_h1 [(size_t)NN * 4];
__device__ float4 g_S  [(size_t)NN * 2];
__device__ float  g_red[64];  // v[i]=g_red[i] (i<10); T[i][k]=g_red[10+i*5+k]
__device__ int    g_is64;
__device__ unsigned int g_barA, g_barB, g_count;   // zero-init; reset by last block

// ---------------------------------------------------------------------------
__device__ __forceinline__ void grid_barrier(unsigned int* bar, int nblocks)
{
    __syncthreads();
    if (threadIdx.x == 0) {
        __threadfence();
        atomicAdd(bar, 1u);
        while (*(volatile unsigned int*)bar < (unsigned int)nblocks)
            __nanosleep(32);
        __threadfence();
    }
    __syncthreads();
}

__device__ __forceinline__ void load_edge(const void* ei, int ec, int e,
                                          int& src, int& tgt, int is64)
{
    if (is64) {
        const long long* p = (const long long*)ei;
        src = (int)__ldg(&p[e]);
        tgt = (int)__ldg(&p[(size_t)ec + e]);
    } else {
        const int* p = (const int*)ei;
        src = __ldg(&p[e]);
        tgt = __ldg(&p[(size_t)ec + e]);
    }
}

// ---------------------------------------------------------------------------
__global__ __launch_bounds__(NTHR, 2)
void k_all(const float* __restrict__ x,
           const float* __restrict__ W1e, const float* __restrict__ b1e,
           const float* __restrict__ Wr1, const float* __restrict__ bb1,
           const void* __restrict__ ei, const float4* __restrict__ attr,
           const float* __restrict__ Wr2, const float* __restrict__ bb2,
           const float* __restrict__ W2e, const float* __restrict__ b2e,
           const float* __restrict__ w1, const float* __restrict__ bw1,
           const float* __restrict__ w2, const float* __restrict__ bw2,
           const float* __restrict__ w3, const float* __restrict__ bw3,
           float* __restrict__ out, int n, int ec, int out_size)
{
    __shared__ float sW[720], sB[180], sWr[180], sBB[16];
    __shared__ float sx[128 * 18];
    __shared__ float sh[8][64];

    const int nblocks = gridDim.x;
    const int gstride = nblocks * NTHR;
    const int g0 = blockIdx.x * NTHR + threadIdx.x;

    // ================= PHASE 0: zero S + g_red; dtype sniff ================
    {
        float4 z = make_float4(0.f, 0.f, 0.f, 0.f);
        for (int i = g0; i < 2 * n; i += gstride) g_S[i] = z;
        if (blockIdx.x == 0) {
            if (threadIdx.x < 64) g_red[threadIdx.x] = 0.f;
            __shared__ int ok;
            if (threadIdx.x == 0) ok = 1;
            __syncthreads();
            const long long* p = (const long long*)ei;
            int m = ec < 128 ? ec : 128;
            if (threadIdx.x < m) {
                long long v = p[threadIdx.x];
                if (v < 0 || v >= n) ok = 0;
            }
            __syncthreads();
            if (threadIdx.x == 0) g_is64 = ok;
        }
    }
    grid_barrier(&g_barA, nblocks);
    const int is64 = g_is64;

    // ================= PHASE A: node tables + S build ======================
    // node role: tiles of 128 nodes, 2 threads/node (half o-range each)
    {
        for (int i = threadIdx.x; i < 720; i += NTHR) sW[i] = W1e[i];
        for (int i = threadIdx.x; i < 180; i += NTHR) { sB[i] = b1e[i]; sWr[i] = Wr1[i]; }
        if (threadIdx.x < 10) sBB[threadIdx.x] = bb1[threadIdx.x];

        int ntiles = (n + 127) / 128;
        for (int tile = blockIdx.x; tile < ntiles; tile += nblocks) {
            int nd0 = tile * 128;
            int cnt = n - nd0; if (cnt > 128) cnt = 128;
            __syncthreads();
            for (int i = threadIdx.x; i < cnt * 18; i += NTHR)
                sx[i] = __ldg(&x[(size_t)nd0 * 18 + i]);
            __syncthreads();

            int ndl  = threadIdx.x >> 1;
            int half = threadIdx.x & 1;
            if (ndl < cnt) {
                int nd = nd0 + ndl;
                float xv[18];
                #pragma unroll
                for (int i = 0; i < 18; i++) xv[i] = sx[ndl * 18 + i];

                __half2* prow = (__half2*)(g_P1h + (size_t)nd * 8);
                __half*  qrow = (__half*)prow;
                float*   hrow = (float*)(g_h1 + (size_t)nd * 4);

                int o0 = half * 5;
                #pragma unroll
                for (int oo = 0; oo < 5; oo++) {
                    int o = o0 + oo;
                    float p0 = 0.f, p1 = 0.f, p2 = 0.f, p3 = 0.f, q = 0.f, h = 0.f;
                    #pragma unroll
                    for (int i = 0; i < 18; i++) {
                        int r = i * 10 + o;
                        float xi = xv[i];
                        p0 += xi * sW[r * 4 + 0];
                        p1 += xi * sW[r * 4 + 1];
                        p2 += xi * sW[r * 4 + 2];
                        p3 += xi * sW[r * 4 + 3];
                        q  += xi * sB[r];
                        h  += xi * sWr[r];
                    }
                    prow[o * 2 + 0] = __floats2half2_rn(p0, p1);
                    prow[o * 2 + 1] = __floats2half2_rn(p2, p3);
                    qrow[40 + o]    = __float2half_rn(q);
                    hrow[o]         = h + sBB[o];
                }
            }
        }

        // edge role: S[src] += (attr, 1)
        for (int e = g0; e < ec; e += gstride) {
            int src;
            if (is64) src = (int)__ldg(&((const long long*)ei)[e]);
            else      src = __ldg(&((const int*)ei)[e]);
            float4 a = __ldg(&attr[e]);
            float* s = (float*)(g_S + (size_t)src * 2);
            asm volatile("red.global.add.v4.f32 [%0], {%1,%2,%3,%4};"
                         :: "l"(s), "f"(a.x), "f"(a.y), "f"(a.z), "f"(a.w) : "memory");
            asm volatile("red.global.add.f32 [%0], %1;"
                         :: "l"(s + 4), "f"(1.0f) : "memory");
        }
    }
    grid_barrier(&g_barB, nblocks);

    // ================= PHASE B: reductions + MLP ===========================
    float v[10];
    float T[50];
    #pragma unroll
    for (int i = 0; i < 10; i++) v[i] = 0.f;
    #pragma unroll
    for (int i = 0; i < 50; i++) T[i] = 0.f;

    // root contribution (streaming)
    for (int nd = g0; nd < n; nd += gstride) {
        const float* hr = (const float*)(g_h1 + (size_t)nd * 4);
        const float* sr = (const float*)(g_S  + (size_t)nd * 2);
        float4 ha = *(const float4*)hr;
        float4 hb = *(const float4*)(hr + 4);
        float2 hc = *(const float2*)(hr + 8);
        float hv[10] = {ha.x, ha.y, ha.z, ha.w, hb.x, hb.y, hb.z, hb.w, hc.x, hc.y};
        float4 s4 = *(const float4*)sr;
        float  sd = sr[4];
        #pragma unroll
        for (int i = 0; i < 10; i++) {
            float hi = hv[i];
            v[i] += hi;
            T[i * 5 + 0] += hi * s4.x;
            T[i * 5 + 1] += hi * s4.y;
            T[i * 5 + 2] += hi * s4.z;
            T[i * 5 + 3] += hi * s4.w;
            T[i * 5 + 4] += hi * sd;
        }
    }

    // message contribution (gather, no atomics)
    for (int e = g0; e < ec; e += gstride) {
        int src, tgt;
        load_edge(ei, ec, e, src, tgt, is64);
        float4 a = __ldg(&attr[e]);

        const float4* r = g_P1h + (size_t)src * 8;
        float4 raw[7];
        #pragma unroll
        for (int i = 0; i < 6; i++) raw[i] = __ldg(&r[i]);
        raw[6].x = __ldg((const float*)r + 24);
        const __half2* hp = (const __half2*)raw;

        float m[10];
        #pragma unroll
        for (int o = 0; o < 10; o++) {
            float2 pab = __half22float2(hp[o * 2 + 0]);
            float2 pcd = __half22float2(hp[o * 2 + 1]);
            m[o] = a.x * pab.x + a.y * pab.y + a.z * pcd.x + a.w * pcd.y;
        }
        #pragma unroll
        for (int j = 0; j < 5; j++) {
            float2 q2 = __half22float2(hp[20 + j]);
            m[j * 2 + 0] += q2.x;
            m[j * 2 + 1] += q2.y;
        }

        const float* sr = (const float*)(g_S + (size_t)tgt * 2);
        float4 s4 = __ldg((const float4*)sr);
        float  sd = __ldg(sr + 4);

        #pragma unroll
        for (int i = 0; i < 10; i++) {
            float mi = m[i];
            v[i] += mi;
            T[i * 5 + 0] += mi * s4.x;
            T[i * 5 + 1] += mi * s4.y;
            T[i * 5 + 2] += mi * s4.z;
            T[i * 5 + 3] += mi * s4.w;
            T[i * 5 + 4] += mi * sd;
        }
    }

    // block reduce -> g_red
    #pragma unroll
    for (int off = 16; off > 0; off >>= 1) {
        #pragma unroll
        for (int i = 0; i < 10; i++) v[i] += __shfl_down_sync(0xffffffffu, v[i], off);
        #pragma unroll
        for (int i = 0; i < 50; i++) T[i] += __shfl_down_sync(0xffffffffu, T[i], off);
    }
    int w = threadIdx.x >> 5, l = threadIdx.x & 31;
    __syncthreads();
    if (l == 0) {
        #pragma unroll
        for (int i = 0; i < 10; i++) sh[w][i] = v[i];
        #pragma unroll
        for (int i = 0; i < 50; i++) sh[w][10 + i] = T[i];
    }
    __syncthreads();
    if (threadIdx.x < 60) {
        float t = 0.f;
        #pragma unroll
        for (int ww = 0; ww < NTHR / 32; ww++) t += sh[ww][threadIdx.x];
        atomicAdd(&g_red[threadIdx.x], t);
    }
    __threadfence();
    __syncthreads();

    // last block: final MLP + counter reset for next replay
    __shared__ int isLast;
    if (threadIdx.x == 0) {
        unsigned int prev = atomicAdd(&g_count, 1u);
        isLast = (prev == (unsigned int)(nblocks - 1)) ? 1 : 0;
    }
    __syncthreads();
    if (!isLast) return;

    if (threadIdx.x == 0) {   // reset barriers/counter for the next graph replay
        *(volatile unsigned int*)&g_barA  = 0u;
        *(volatile unsigned int*)&g_barB  = 0u;
        *(volatile unsigned int*)&g_count = 0u;
    }

    volatile float* gr = g_red;
    __shared__ float g[8];
    int lane = threadIdx.x;
    float invn = 1.0f / (float)n;
    if (lane < 7) {
        int o = lane;
        float s = (float)n * bb2[o];
        #pragma unroll
        for (int i = 0; i < 10; i++) {
            float vi = gr[i];
            s += vi * Wr2[i * 7 + o];
            int r = i * 7 + o;
            #pragma unroll
            for (int k = 0; k < 4; k++) s += gr[10 + i * 5 + k] * W2e[r * 4 + k];
            s += gr[10 + i * 5 + 4] * b2e[r];
        }
        g[o] = s * invn;
    }
    __syncthreads();
    if (lane == 0) {
        float gg[7];
        #pragma unroll
        for (int k = 0; k < 7; k++) gg[k] = g[k];
        float g1[20];
        for (int j = 0; j < 20; j++) {
            float val = bw1[j];
            #pragma unroll
            for (int k = 0; k < 7; k++) val += gg[k] * w1[j * 7 + k];
            g1[j] = val > 0.f ? val : 0.f;
        }
        float g2[10];
        for (int j = 0; j < 10; j++) {
            float val = bw2[j];
            #pragma unroll
            for (int k = 0; k < 20; k++) val += g1[k] * w2[j * 20 + k];
            g2[j] = val > 0.f ? val : 0.f;
        }
        float z = bw3[0];
        #pragma unroll
        for (int k = 0; k < 10; k++) z += g2[k] * w3[k];
        float r = 1.0f / (1.0f + expf(-z));
        for (int i = 0; i < out_size; i++) out[i] = r;
    }
}

// ---------------------------------------------------------------------------
extern "C" void kernel_launch(void* const* d_in, const int* in_sizes, int n_in,
                              void* d_out, int out_size)
{
    const float*  x    = (const float*)d_in[0];
    const void*   ei   = d_in[1];
    const float4* attr = (const float4*)d_in[2];
    const float* W1e = (const float*)d_in[3];
    const float* b1e = (const float*)d_in[4];
    const float* Wr1 = (const float*)d_in[5];
    const float* bb1 = (const float*)d_in[6];
    const float* W2e = (const float*)d_in[7];
    const float* b2e = (const float*)d_in[8];
    const float* Wr2 = (const float*)d_in[9];
    const float* bb2 = (const float*)d_in[10];
    const float* w1  = (const float*)d_in[11];
    const float* bw1 = (const float*)d_in[12];
    const float* w2  = (const float*)d_in[13];
    const float* bw2 = (const float*)d_in[14];
    const float* w3  = (const float*)d_in[15];
    const float* bw3 = (const float*)d_in[16];

    int n = in_sizes[0] / 18;
    int e = in_sizes[2] / 4;
    if (n > NN) n = NN;
    if (e > NE) e = NE;

    // Residency-safe grid: occupancy-derived blocks/SM (launch_bounds caps at 2).
    int dev = 0, sms = 148, bpsm = 0;
    cudaGetDevice(&dev);
    cudaDeviceGetAttribute(&sms, cudaDevAttrMultiProcessorCount, dev);
    cudaOccupancyMaxActiveBlocksPerMultiprocessor(&bpsm, k_all, NTHR, 0);
    if (bpsm < 1) bpsm = 1;
    if (bpsm > 2) bpsm = 2;
    int grid = sms * bpsm;

    k_all<<<grid, NTHR>>>(x, W1e, b1e, Wr1, bb1, ei, attr,
                          Wr2, bb2, W2e, b2e, w1, bw1, w2, bw2, w3, bw3,
                          (float*)d_out, n, e, out_size);
}